// round 13
// baseline (speedup 1.0000x reference)
#include <cuda_runtime.h>
#include <math.h>
#include <stdint.h>

// Problem constants (fixed shapes)
#define BN 2048
#define ZD 512
#define HD 384
#define TN 32
#define G4 (4*HD)              // 1536
#define OUT_STRIDE (TN*ZD)     // 16384
#define E_STRIDE ((TN-1)*ZD)   // 15872
#define HC_STRIDE (2*HD)       // 768
#define SEQ ((TN-1)*BN)        // 63488

#define LDS 36                 // smem row stride in words (32 + 4 pad)

// Scratch (allocation-free: __device__ globals)
__device__ float g_h0[(size_t)BN*HD];
__device__ float g_h1[(size_t)BN*HD];
__device__ float g_c[(size_t)BN*HD];
__device__ float g_hc[(size_t)SEQ*HC_STRIDE];
__device__ float g_mid[(size_t)SEQ*ZD];
__device__ float g_outTf[(size_t)BN*ZD];
__device__ float g_WihEnc_t[(size_t)G4*ZD];
__device__ float g_Wih_t[(size_t)G4*ZD];
__device__ float g_Whh_t[(size_t)G4*HD];
__device__ float g_bsumEnc[G4];
__device__ float g_bsum[G4];
__device__ float g_fc1_t[(size_t)ZD*HC_STRIDE];
__device__ float g_fc2_t[(size_t)ZD*ZD];
__device__ float g_wT[(size_t)ZD*HD];
// Persistent-kernel group barriers (16 groups of 8 CTAs). Zero-init; every
// launch leaves them back at {0,0} (even barrier count restores the sense).
__device__ unsigned g_bcnt[16];
__device__ unsigned g_bflag[16];

__device__ __forceinline__ float sigf(float x) { return 1.0f / (1.0f + __expf(-x)); }

__device__ __forceinline__ uint32_t f2tf(float x) {
    uint32_t r;
    asm("cvt.rna.tf32.f32 %0, %1;" : "=r"(r) : "f"(x));
    return r;
}
__device__ __forceinline__ float rtf(float x) { return __uint_as_float(f2tf(x)); }

__device__ __forceinline__ uint32_t smem_u32(const void* p) {
    uint32_t a;
    asm("{ .reg .u64 t; cvta.to.shared.u64 t, %1; cvt.u32.u64 %0, t; }" : "=r"(a) : "l"(p));
    return a;
}

__device__ __forceinline__ void mma_tf32(
    float* c, uint32_t a0, uint32_t a1, uint32_t a2, uint32_t a3,
    uint32_t b0, uint32_t b1)
{
    asm volatile(
        "mma.sync.aligned.m16n8k8.row.col.f32.tf32.tf32.f32 "
        "{%0,%1,%2,%3}, {%4,%5,%6,%7}, {%8,%9}, {%0,%1,%2,%3};"
        : "+f"(c[0]), "+f"(c[1]), "+f"(c[2]), "+f"(c[3])
        : "r"(a0), "r"(a1), "r"(a2), "r"(a3), "r"(b0), "r"(b1));
}

__device__ __forceinline__ void ldm4(uint32_t* r, uint32_t addr) {
    asm volatile("ldmatrix.sync.aligned.m8n8.x4.shared.b16 {%0,%1,%2,%3}, [%4];"
        : "=r"(r[0]), "=r"(r[1]), "=r"(r[2]), "=r"(r[3]) : "r"(addr));
}

// L2-only async copy (cg): REQUIRED in the persistent kernel — peer CTAs on
// other SMs rewrite these tiles between phases and L1 is not coherent.
__device__ __forceinline__ void cpa16(uint32_t dst, const void* src) {
    asm volatile("cp.async.cg.shared.global [%0], [%1], 16;" :: "r"(dst), "l"(src));
}

__device__ __forceinline__ unsigned vload(const unsigned* p) {
    unsigned v;
    asm volatile("ld.volatile.global.u32 %0, [%1];" : "=r"(v) : "l"(p));
    return v;
}

// 8-CTA sense-reversing barrier. Barrier b sets flag to (~b)&1; last arriver
// resets the count. After an even number of barriers, state is {0,0} again.
__device__ __forceinline__ void group_barrier(unsigned* cnt, unsigned* flag, int b) {
    __syncthreads();
    if (threadIdx.x == 0) {
        const unsigned want = (unsigned)(~b) & 1u;
        __threadfence();
        unsigned old = atomicAdd(cnt, 1u);
        if (old == 7u) {
            asm volatile("st.volatile.global.u32 [%0], %1;" :: "l"(cnt), "r"(0u));
            __threadfence();
            asm volatile("st.volatile.global.u32 [%0], %1;" :: "l"(flag), "r"(want));
        } else {
            while (vload(flag) != want) __nanosleep(64);
        }
        __threadfence();
    }
    __syncthreads();
}

// Issue cp.async for a [ROWS x 32 floats] K-major tile (row stride LDS words).
template<int ROWS>
__device__ __forceinline__ void issue_tile(
    const float* __restrict__ G, int row0, int ld, int k0, uint32_t smemBase, int tid)
{
#pragma unroll
    for (int s = tid; s < ROWS * 8; s += 256) {
        const int row = s >> 3, c4 = s & 7;
        cpa16(smemBase + (uint32_t)(row * LDS + c4 * 4) * 4u,
              G + (size_t)(row0 + row) * ld + k0 + c4 * 4);
    }
}

// ---------------------------------------------------------------------------
// GEMM mainloop (device function): tf32 mma.sync, NT, cp.async double-buffered,
// ldmatrix fragments. 256 thr = 8 warps (4m x 2n). Tile 128 x (NF*16), K chunk
// 32, dual-A accumulated. Fills acc; caller owns the epilogue.
// ---------------------------------------------------------------------------
template<int NF>
__device__ __forceinline__ void run_gemm(
    float (&acc)[2][NF][4],
    const float* __restrict__ A1, int lda1, int K1,
    const float* __restrict__ A2, int lda2, int K2,
    const float* __restrict__ B1, int ldb1,
    const float* __restrict__ B2, int ldb2,
    int bm, int bn, uint32_t smBase)
{
    constexpr int BROWS = NF * 16;
    constexpr int AW    = 128 * LDS;
    constexpr int TILEW = (128 + BROWS) * LDS;

    const int tid = threadIdx.x;
    const int wid = tid >> 5, lane = tid & 31;
    const int wm  = (wid >> 1) * 32;
    const int wn  = (wid & 1) * (NF * 8);

#pragma unroll
    for (int mi = 0; mi < 2; mi++)
#pragma unroll
        for (int ni = 0; ni < NF; ni++)
#pragma unroll
            for (int j = 0; j < 4; j++) acc[mi][ni][j] = 0.0f;

    const int nch1 = K1 >> 5;
    const int nch  = nch1 + (K2 >> 5);

    auto chunkSrc = [&](int c, const float*& Ap, const float*& Bp,
                        int& la, int& lb, int& k0) {
        if (c < nch1) { Ap = A1; Bp = B1; la = lda1; lb = ldb1; k0 = c << 5; }
        else          { Ap = A2; Bp = B2; la = lda2; lb = ldb2; k0 = (c - nch1) << 5; }
    };

    const int a_r = (lane & 7) + ((lane >> 3) & 1) * 8;
    const int a_c = ((lane >> 4) & 1) * 4;
    const int b_r = ((lane >> 4) & 1) * 8 + (lane & 7);
    const int b_c = ((lane >> 3) & 1) * 4;
    const uint32_t aOfs0 = (uint32_t)((wm + a_r) * LDS + a_c) * 4u;
    const uint32_t aOfs1 = aOfs0 + 16u * LDS * 4u;
    const uint32_t bOfs  = (uint32_t)(AW + (wn + b_r) * LDS + b_c) * 4u;

    {
        const float *Ap, *Bp; int la, lb, k0;
        chunkSrc(0, Ap, Bp, la, lb, k0);
        issue_tile<128>(Ap, bm, la, k0, smBase, tid);
        issue_tile<BROWS>(Bp, bn, lb, k0, smBase + AW * 4, tid);
        asm volatile("cp.async.commit_group;" ::: "memory");
    }

#pragma unroll 1
    for (int c = 0; c < nch; ++c) {
        const uint32_t pb = smBase + (uint32_t)(c & 1) * TILEW * 4u;
        if (c + 1 < nch) {
            const float *Ap, *Bp; int la, lb, k0;
            chunkSrc(c + 1, Ap, Bp, la, lb, k0);
            const uint32_t nb = smBase + (uint32_t)((c + 1) & 1) * TILEW * 4u;
            issue_tile<128>(Ap, bm, la, k0, nb, tid);
            issue_tile<BROWS>(Bp, bn, lb, k0, nb + AW * 4, tid);
            asm volatile("cp.async.commit_group;" ::: "memory");
            asm volatile("cp.async.wait_group 1;" ::: "memory");
        } else {
            asm volatile("cp.async.wait_group 0;" ::: "memory");
        }
        __syncthreads();
#pragma unroll
        for (int s = 0; s < 4; s++) {
            uint32_t a[2][4], bf[NF][2];
            ldm4(a[0], pb + aOfs0 + s * 32);
            ldm4(a[1], pb + aOfs1 + s * 32);
#pragma unroll
            for (int j = 0; j < NF / 2; j++) {
                uint32_t t[4];
                ldm4(t, pb + bOfs + (uint32_t)j * (16u * LDS * 4u) + s * 32);
                bf[2*j][0]   = t[0]; bf[2*j][1]   = t[1];
                bf[2*j+1][0] = t[2]; bf[2*j+1][1] = t[3];
            }
#pragma unroll
            for (int mi = 0; mi < 2; mi++)
#pragma unroll
                for (int ni = 0; ni < NF; ni++)
                    mma_tf32(acc[mi][ni], a[mi][0], a[mi][1], a[mi][2], a[mi][3],
                             bf[ni][0], bf[ni][1]);
        }
        __syncthreads();
    }
}

// Fused LSTM cell epilogue (NF=12, gate-interleaved permuted weights).
// col P = 96*Wg + 8*(4v+g) + 2t + b  <->  unit j = 24*Wg + 6t + 3b + v.
__device__ __forceinline__ void lstm_epilogue(
    float (&acc)[2][12][4], const float* __restrict__ bias,
    float* __restrict__ hOut, float* __restrict__ cPtr, int useC,
    float* __restrict__ hcRow, int hcStride, int bm, int bx)
{
    const int tid = threadIdx.x;
    const int wid = tid >> 5, lane = tid & 31;
    const int grp = lane >> 2, tig = lane & 3;
    const int wm  = (wid >> 1) * 32;
    const int Wg  = bx * 2 + (wid & 1);
    const int jbase = 24 * Wg + 6 * tig;
    float bs[2][3][4];
    const float* bp = bias + 96 * Wg + 2 * tig;
#pragma unroll
    for (int b2 = 0; b2 < 2; b2++)
#pragma unroll
        for (int v = 0; v < 3; v++)
#pragma unroll
            for (int g = 0; g < 4; g++)
                bs[b2][v][g] = bp[8 * (4 * v + g) + b2];
#pragma unroll
    for (int mi = 0; mi < 2; mi++) {
#pragma unroll
        for (int rr = 0; rr < 2; rr++) {
            const int R = bm + wm + mi * 16 + grp + rr * 8;
#pragma unroll
            for (int b2 = 0; b2 < 2; b2++) {
#pragma unroll
                for (int v = 0; v < 3; v++) {
                    const float gi = acc[mi][4*v+0][rr*2+b2] + bs[b2][v][0];
                    const float gf = acc[mi][4*v+1][rr*2+b2] + bs[b2][v][1];
                    const float gg = acc[mi][4*v+2][rr*2+b2] + bs[b2][v][2];
                    const float go = acc[mi][4*v+3][rr*2+b2] + bs[b2][v][3];
                    const int j = jbase + 3 * b2 + v;
                    float cn = sigf(gi) * tanhf(gg);
                    if (useC) cn += sigf(gf) * cPtr[(size_t)R * HD + j];
                    const float hn = sigf(go) * tanhf(cn);
                    cPtr[(size_t)R * HD + j] = cn;
                    hOut[(size_t)R * HD + j] = rtf(hn);
                    if (hcRow) {
                        hcRow[(size_t)R * hcStride + j]      = rtf(hn);
                        hcRow[(size_t)R * hcStride + HD + j] = rtf(cn);
                    }
                }
            }
        }
    }
}

// Residual/tanh epilogue (NF=4): out = outPrev + 0.2*tanh(acc+bias);
// writes out (exact), e (exact, optional), outTf (tf32-rounded).
__device__ __forceinline__ void mul_epilogue(
    float (&acc)[2][4][4], const float* __restrict__ bias,
    float* __restrict__ C, const float* __restrict__ outPrev,
    float* __restrict__ ePtr, float* __restrict__ tfPtr, int bm, int bn)
{
    const int tid = threadIdx.x;
    const int wid = tid >> 5, lane = tid & 31;
    const int grp = lane >> 2, tig = lane & 3;
    const int wm  = (wid >> 1) * 32;
    const int wn  = (wid & 1) * 32;
#pragma unroll
    for (int mi = 0; mi < 2; mi++) {
        const int r0 = bm + wm + mi * 16 + grp;
#pragma unroll
        for (int ni = 0; ni < 4; ni++) {
            const int col = bn + wn + ni * 8 + 2 * tig;
#pragma unroll
            for (int rr = 0; rr < 2; rr++) {
                const int row = r0 + rr * 8;
                const float v0 = acc[mi][ni][rr*2+0], v1 = acc[mi][ni][rr*2+1];
                float2 op = *(const float2*)&outPrev[(size_t)row * OUT_STRIDE + col];
                float2 o;
                o.x = op.x + 0.2f * tanhf(v0 + bias[col]);
                o.y = op.y + 0.2f * tanhf(v1 + bias[col + 1]);
                *(float2*)&C[(size_t)row * OUT_STRIDE + col] = o;
                if (ePtr) *(float2*)&ePtr[(size_t)row * E_STRIDE + col] = o;
                *(float2*)&tfPtr[(size_t)row * ZD + col] = make_float2(rtf(o.x), rtf(o.y));
            }
        }
    }
}

// ---------------------------------------------------------------------------
// Persistent recurrence kernel: grid (8, 16) = 128 CTAs, all co-resident.
// Group = 8 CTAs sharing blockIdx.y (one 128-row batch tile); groups are
// fully independent. 62 group barriers (even -> barrier state self-restores).
// ---------------------------------------------------------------------------
__global__ __launch_bounds__(256) void recurrent_kernel(
    float* __restrict__ out, float* __restrict__ e,
    float* __restrict__ outTf,
    float* __restrict__ h0, float* __restrict__ h1, float* __restrict__ c,
    float* __restrict__ hc,
    const float* __restrict__ WihEnc_t, const float* __restrict__ bsumEnc,
    const float* __restrict__ Wih_t, const float* __restrict__ Whh_t,
    const float* __restrict__ bsum,
    const float* __restrict__ wT, const float* __restrict__ b)
{
    extern __shared__ uint32_t sm[];
    const uint32_t smBase = smem_u32(sm);
    const int bx  = blockIdx.x;       // 0..7
    const int gid = blockIdx.y;       // 0..15
    const int bm  = gid * 128;
    unsigned* cnt  = &g_bcnt[gid];
    unsigned* flag = &g_bflag[gid];
    int bb = 0;

    // Encoder: gates = round(z) @ WihEnc^T (h0 = c0 = 0), fused cell -> h0, c
    {
        float acc[2][12][4];
        run_gemm<12>(acc, outTf, ZD, ZD, nullptr, 0, 0,
                     WihEnc_t, ZD, nullptr, 0, bm, bx * 192, smBase);
        lstm_epilogue(acc, bsumEnc, h0, c, 0, nullptr, 0, bm, bx);
    }
    group_barrier(cnt, flag, bb++);

#pragma unroll 1
    for (int k = 0; k < TN - 1; ++k) {
        float* hIn  = (k & 1) ? h1 : h0;
        float* hNew = (k & 1) ? h0 : h1;
        {   // gates = outTf @ Wih^T + hIn @ Whh^T; fused cell -> hNew, c, hc row k
            float acc[2][12][4];
            run_gemm<12>(acc, outTf, ZD, ZD, hIn, HD, HD,
                         Wih_t, ZD, Whh_t, HD, bm, bx * 192, smBase);
            lstm_epilogue(acc, bsum, hNew, c, 1,
                          hc + (size_t)k * HC_STRIDE, (TN - 1) * HC_STRIDE, bm, bx);
        }
        group_barrier(cnt, flag, bb++);
        {   // out_{k+1} = out_k + 0.2*tanh(hNew @ wT^T + b); e row k+1; outTf
            float acc[2][4][4];
            run_gemm<4>(acc, hNew, HD, HD, nullptr, 0, 0,
                        wT, HD, nullptr, 0, bm, bx * 64, smBase);
            mul_epilogue(acc, b,
                         out + (size_t)(k + 1) * ZD,
                         out + (size_t)k * ZD,
                         (k + 1 <= TN - 2) ? (e + (size_t)(k + 1) * ZD) : nullptr,
                         outTf, bm, bx * 64);
        }
        if (k < TN - 2) group_barrier(cnt, flag, bb++);  // total 62 barriers (even)
    }
}

// ---------------------------------------------------------------------------
// Standalone fc GEMM (NF=8): EPI 1 = round_tf(relu(acc+bias)), 2 = acc+bias
// ---------------------------------------------------------------------------
template<int EPI>
__global__ __launch_bounds__(256) void fc_gemm(
    const float* __restrict__ A, int lda, int K,
    const float* __restrict__ B, int ldb,
    const float* __restrict__ bias,
    float* __restrict__ C, int ldc)
{
    extern __shared__ uint32_t sm[];
    const uint32_t smBase = smem_u32(sm);
    const int tid = threadIdx.x;
    const int wid = tid >> 5, lane = tid & 31;
    const int grp = lane >> 2, tig = lane & 3;
    const int wm  = (wid >> 1) * 32;
    const int wn  = (wid & 1) * 64;
    const int bm  = blockIdx.y * 128;
    const int bn  = blockIdx.x * 128;

    float acc[2][8][4];
    run_gemm<8>(acc, A, lda, K, nullptr, 0, 0, B, ldb, nullptr, 0, bm, bn, smBase);

#pragma unroll
    for (int mi = 0; mi < 2; mi++) {
        const int r0 = bm + wm + mi * 16 + grp;
#pragma unroll
        for (int ni = 0; ni < 8; ni++) {
            const int col = bn + wn + ni * 8 + 2 * tig;
#pragma unroll
            for (int rr = 0; rr < 2; rr++) {
                const int row = r0 + rr * 8;
                float v0 = acc[mi][ni][rr*2+0] + bias[col];
                float v1 = acc[mi][ni][rr*2+1] + bias[col + 1];
                if (EPI == 1) {
                    v0 = rtf(fmaxf(v0, 0.f));
                    v1 = rtf(fmaxf(v1, 0.f));
                }
                *(float2*)&C[(size_t)row * ldc + col] = make_float2(v0, v1);
            }
        }
    }
}

// ---------------------------------------------------------------------------
// Setup kernels
// ---------------------------------------------------------------------------
__global__ void init_out(const float* __restrict__ z,
                         float* __restrict__ out, float* __restrict__ e,
                         float* __restrict__ outTf)
{
    int idx = blockIdx.x * blockDim.x + threadIdx.x;
    if (idx >= BN * ZD) return;
    int b = idx >> 9, n = idx & 511;
    float v = z[idx];
    out[(size_t)b * OUT_STRIDE + n] = v;
    e[(size_t)b * E_STRIDE + n] = v;
    outTf[idx] = rtf(v);
}

__global__ void round_copy(const float* __restrict__ src, float* __restrict__ dst, int n)
{
    int idx = blockIdx.x * blockDim.x + threadIdx.x;
    if (idx < n) dst[idx] = rtf(src[idx]);
}

__global__ void perm_weight(const float* __restrict__ src, float* __restrict__ dst, int K)
{
    int idx = blockIdx.x * blockDim.x + threadIdx.x;
    if (idx >= G4 * K) return;
    int P = idx / K, k = idx - P * K;
    int W = P / 96, r = P - W * 96;
    int k8 = r >> 3, t = (r >> 1) & 3, b2 = r & 1;
    int v = k8 >> 2, g = k8 & 3;
    int j = 24 * W + 6 * t + 3 * b2 + v;
    dst[idx] = rtf(src[(size_t)(g * HD + j) * K + k]);
}

__global__ void perm_bias(const float* __restrict__ b1, const float* __restrict__ b2,
                          float* __restrict__ dst)
{
    int P = blockIdx.x * blockDim.x + threadIdx.x;
    if (P >= G4) return;
    int W = P / 96, r = P - W * 96;
    int k8 = r >> 3, t = (r >> 1) & 3, bb = r & 1;
    int v = k8 >> 2, g = k8 & 3;
    int j = 24 * W + 6 * t + 3 * bb + v;
    dst[P] = b1[g * HD + j] + b2[g * HD + j];
}

__global__ void transpose_round_w(const float* __restrict__ w, float* __restrict__ wT)
{
    int idx = blockIdx.x * blockDim.x + threadIdx.x;
    if (idx >= ZD * HD) return;
    int n = idx / HD, k = idx - n * HD;
    wT[idx] = rtf(w[(size_t)k * ZD + n]);
}

extern "C" void kernel_launch(void* const* d_in, const int* in_sizes, int n_in,
                              void* d_out, int out_size)
{
    (void)in_sizes; (void)n_in; (void)out_size;
    const float* z       = (const float*)d_in[0];
    const float* Wih_enc = (const float*)d_in[1];
    const float* bih_enc = (const float*)d_in[3];
    const float* bhh_enc = (const float*)d_in[4];
    const float* Wih     = (const float*)d_in[5];
    const float* Whh     = (const float*)d_in[6];
    const float* bih     = (const float*)d_in[7];
    const float* bhh     = (const float*)d_in[8];
    const float* w       = (const float*)d_in[9];
    const float* b       = (const float*)d_in[10];
    const float* fc1_w   = (const float*)d_in[11];
    const float* fc1_b   = (const float*)d_in[12];
    const float* fc2_w   = (const float*)d_in[13];
    const float* fc2_b   = (const float*)d_in[14];
    // d_in[2] (Whh_enc) unused: h0 = 0 so the enc Whh term vanishes

    float* out  = (float*)d_out;
    float* e    = out + (size_t)BN * TN * ZD;
    float* erec = e + (size_t)SEQ * ZD;

    float *h0, *h1, *c, *hc, *mid, *outTf;
    float *WihEnc_t, *Wih_t, *Whh_t, *bsumEnc, *bsum, *fc1_t, *fc2_t, *wT;
    cudaGetSymbolAddress((void**)&h0,       g_h0);
    cudaGetSymbolAddress((void**)&h1,       g_h1);
    cudaGetSymbolAddress((void**)&c,        g_c);
    cudaGetSymbolAddress((void**)&hc,       g_hc);
    cudaGetSymbolAddress((void**)&mid,      g_mid);
    cudaGetSymbolAddress((void**)&outTf,    g_outTf);
    cudaGetSymbolAddress((void**)&WihEnc_t, g_WihEnc_t);
    cudaGetSymbolAddress((void**)&Wih_t,    g_Wih_t);
    cudaGetSymbolAddress((void**)&Whh_t,    g_Whh_t);
    cudaGetSymbolAddress((void**)&bsumEnc,  g_bsumEnc);
    cudaGetSymbolAddress((void**)&bsum,     g_bsum);
    cudaGetSymbolAddress((void**)&fc1_t,    g_fc1_t);
    cudaGetSymbolAddress((void**)&fc2_t,    g_fc2_t);
    cudaGetSymbolAddress((void**)&wT,       g_wT);

    constexpr int SMEM12 = 2 * (128 + 192) * LDS * 4;  // 92160
    constexpr int SMEM8  = 2 * (128 + 128) * LDS * 4;  // 73728
    cudaFuncSetAttribute(recurrent_kernel, cudaFuncAttributeMaxDynamicSharedMemorySize, SMEM12);
    cudaFuncSetAttribute(fc_gemm<1>, cudaFuncAttributeMaxDynamicSharedMemorySize, SMEM8);
    cudaFuncSetAttribute(fc_gemm<2>, cudaFuncAttributeMaxDynamicSharedMemorySize, SMEM8);

    // One-time setup (cheap)
    init_out<<<(BN * ZD) / 256, 256>>>(z, out, e, outTf);
    perm_weight<<<(G4 * ZD) / 256, 256>>>(Wih_enc, WihEnc_t, ZD);
    perm_weight<<<(G4 * ZD) / 256, 256>>>(Wih, Wih_t, ZD);
    perm_weight<<<(G4 * HD) / 256, 256>>>(Whh, Whh_t, HD);
    perm_bias<<<G4 / 256, 256>>>(bih_enc, bhh_enc, bsumEnc);
    perm_bias<<<G4 / 256, 256>>>(bih, bhh, bsum);
    round_copy<<<(ZD * HC_STRIDE) / 256, 256>>>(fc1_w, fc1_t, ZD * HC_STRIDE);
    round_copy<<<(ZD * ZD) / 256, 256>>>(fc2_w, fc2_t, ZD * ZD);
    transpose_round_w<<<(ZD * HD) / 256, 256>>>(w, wT);

    // Entire recurrence: ONE persistent kernel (128 co-resident CTAs)
    recurrent_kernel<<<dim3(8, 16), 256, SMEM12>>>(
        out, e, outTf, h0, h1, c, hc,
        WihEnc_t, bsumEnc, Wih_t, Whh_t, bsum, wT, b);

    // e_rec = relu(hc @ fc1^T + fc1_b) @ fc2^T + fc2_b
    fc_gemm<1><<<dim3(ZD / 128, SEQ / 128), 256, SMEM8>>>(
        hc, HC_STRIDE, HC_STRIDE, fc1_t, HC_STRIDE, fc1_b, mid, ZD);
    fc_gemm<2><<<dim3(ZD / 128, SEQ / 128), 256, SMEM8>>>(
        mid, ZD, ZD, fc2_t, ZD, fc2_b, erec, ZD);
}